// round 8
// baseline (speedup 1.0000x reference)
#include <cuda_runtime.h>
#include <cuda_bf16.h>
#include <cstdint>

// ---------------- scratch (device globals: no allocation allowed) ----------
#define MAX_NODES 100000
__device__ __align__(16) float g_sums[(size_t)MAX_NODES * 128];
__device__ float g_counts[MAX_NODES];
// Transposed, k-chunked bf16 hi/lo weights:
// per layer: [kc][split][n][32] ; L1 @0 (131072), L2 @131072, L3 @262144
__device__ __align__(16) __nv_bfloat16 g_Wt[327680];

// ---------------- helpers ---------------------------------------------------
__device__ __forceinline__ uint32_t smem_u32(const void* p) {
    uint32_t a;
    asm("{ .reg .u64 t; cvta.to.shared.u64 t, %1; cvt.u32.u64 %0, t; }"
        : "=r"(a) : "l"(p));
    return a;
}
__device__ __forceinline__ void cp_async16(uint32_t saddr, const void* g) {
    asm volatile("cp.async.cg.shared.global [%0], [%1], 16;" :: "r"(saddr), "l"(g));
}
__device__ __forceinline__ void ldm_x4(uint32_t* r, uint32_t addr) {
    asm volatile("ldmatrix.sync.aligned.m8n8.x4.shared.b16 {%0,%1,%2,%3}, [%4];"
        : "=r"(r[0]), "=r"(r[1]), "=r"(r[2]), "=r"(r[3]) : "r"(addr));
}
__device__ __forceinline__ void mma_bf16(float* c, const uint32_t* a,
                                         uint32_t b0, uint32_t b1) {
    asm volatile("mma.sync.aligned.m16n8k16.row.col.f32.bf16.bf16.f32 "
        "{%0,%1,%2,%3}, {%4,%5,%6,%7}, {%8,%9}, {%0,%1,%2,%3};"
        : "+f"(c[0]), "+f"(c[1]), "+f"(c[2]), "+f"(c[3])
        : "r"(a[0]), "r"(a[1]), "r"(a[2]), "r"(a[3]), "r"(b0), "r"(b1));
}
__device__ __forceinline__ uint32_t pack_bf(__nv_bfloat16 a, __nv_bfloat16 b) {
    return (uint32_t)__bfloat16_as_ushort(a) | ((uint32_t)__bfloat16_as_ushort(b) << 16);
}

// smem layout (bytes)
constexpr int TPB      = 1024;                // 32 warps: 8 per SMSP
constexpr int AS       = 264;                 // A row stride (elements)
constexpr int A_HI_OFF = 0;                   // 128*264*2 = 67584
constexpr int A_LO_OFF = 67584;
constexpr int B_OFF    = 135168;
constexpr int BUFSZ    = 40960;               // one B buffer (OUT=256 worst case)
constexpr int SMEM_TOTAL = B_OFF + 2 * BUFSZ; // 217088

__device__ __forceinline__ void store_split(char* smem, int row, int col,
                                            float v0, float v1) {
    __nv_bfloat16 h0 = __float2bfloat16(v0), h1 = __float2bfloat16(v1);
    __nv_bfloat16 l0 = __float2bfloat16(v0 - __bfloat162float(h0));
    __nv_bfloat16 l1 = __float2bfloat16(v1 - __bfloat162float(h1));
    uint32_t off = (uint32_t)(row * AS + col) * 2;
    *(uint32_t*)(smem + A_HI_OFF + off) = pack_bf(h0, h1);
    *(uint32_t*)(smem + A_LO_OFF + off) = pack_bf(l0, l1);
}

// ---------------- kernel 1: zero the scatter accumulators ------------------
__global__ void zero_kernel(int n_nodes) {
    int i = blockIdx.x * blockDim.x + threadIdx.x;
    int n4 = n_nodes * 32;
    if (i < n4) ((float4*)g_sums)[i] = make_float4(0.f, 0.f, 0.f, 0.f);
    if (i < n_nodes) g_counts[i] = 0.f;
}

// ---------------- kernel 2: scatter-add (vector atomics) -------------------
__global__ void scatter_kernel(const float* __restrict__ edge_attr,
                               const int*   __restrict__ col,
                               int n_edges) {
    int t = blockIdx.x * blockDim.x + threadIdx.x;
    int e = t >> 5;
    int lane = t & 31;
    if (e >= n_edges) return;
    int c = __ldg(col + e);
    float4 v = ((const float4*)edge_attr)[(size_t)e * 32 + lane];
    float* dst = g_sums + (size_t)c * 128 + lane * 4;
    asm volatile("red.global.add.v4.f32 [%0], {%1,%2,%3,%4};"
                 :: "l"(dst), "f"(v.x), "f"(v.y), "f"(v.z), "f"(v.w) : "memory");
    if (lane == 0) atomicAdd(g_counts + c, 1.0f);
}

// ---------------- kernel: prep weights -> g_Wt ------------------------------
// Layout per layer: [kc][split(hi=0,lo=1)][n][32 k] , n-major rows (W^T).
__global__ void prep_kernel(const float* __restrict__ W1,
                            const float* __restrict__ W2,
                            const float* __restrict__ W3) {
    int i = blockIdx.x * blockDim.x + threadIdx.x;
    if (i >= 327680) return;
    const float* W; int base, OUT, e = i;
    if (i < 131072)      { W = W1; base = 0;      OUT = 256; }
    else if (i < 262144) { W = W2; base = 131072; OUT = 256; e -= 131072; }
    else                 { W = W3; base = 262144; OUT = 128; e -= 262144; }
    int per_kc = 2 * OUT * 32;
    int kc  = e / per_kc;
    int rem = e % per_kc;
    int s   = rem / (OUT * 32);
    int r   = rem % (OUT * 32);
    int nn  = r >> 5, kk = r & 31;
    int k   = kc * 32 + kk;
    float w = __ldg(W + (size_t)k * OUT + nn);
    __nv_bfloat16 hi = __float2bfloat16(w);
    __nv_bfloat16 val = s ? __float2bfloat16(w - __bfloat162float(hi)) : hi;
    g_Wt[base + e] = val;
}

// ---------------- B chunk loader (linear cp.async into padded rows) --------
template<int OUT>
__device__ __forceinline__ void load_chunk(uint32_t bdst, const __nv_bfloat16* gsrc) {
    constexpr int UNITS = OUT * 8;         // 16B units in a chunk (both splits)
    constexpr int SSTR  = OUT * 80;        // bytes per split in smem
    #pragma unroll
    for (int u = threadIdx.x; u < UNITS; u += TPB) {
        int s = u / (UNITS / 2);
        int v = u % (UNITS / 2);
        int nn = v >> 2, part = v & 3;
        uint32_t dst = bdst + s * SSTR + nn * 80 + part * 16;
        cp_async16(dst, (const char*)gsrc + (size_t)u * 16);
    }
    asm volatile("cp.async.commit_group;");
}

// ---------------- one MLP layer on HMMA -------------------------------------
// Warp grid: 4 (m) x 8 (n). Invariant at entry: this layer's chunks 0 and 1
// already committed, chunk c in buffer c&1; during the loop chunk kc+2 (or
// the next layer's chunks 0/1) is issued after the compute sync of chunk kc.
// T = IN/32 k-chunks (IN = 256 for all layers).
template<int IN, int OUT, int OUT_NEXT, bool LAST>
__device__ __forceinline__ void run_layer(char* smem, uint32_t sm_base,
                                          const __nv_bfloat16* gW,
                                          const __nv_bfloat16* gW_next,
                                          const float* __restrict__ bias,
                                          float* __restrict__ out_g,
                                          int nbase, int n)
{
    const int lane = threadIdx.x & 31, wid = threadIdx.x >> 5;
    const int wm = wid >> 3, wn = wid & 7;   // 4 x 8 warp grid
    constexpr int NT   = OUT / 64;           // n8-tiles per warp (4 or 2)
    constexpr int T    = IN / 32;            // k-chunks this layer (=8)
    constexpr int SSTR = OUT * 80;           // bytes per split in a B buffer

    const int arow = wm * 32 + (lane & 15);
    const int acol = (lane >> 4) * 8;
    // B ldmatrix lane mapping: lane l -> row (l&7) of matrix l>>3.
    const int b_noff = ((lane >> 4) & 1) * 8 + (lane & 7);
    const int b_kby  = ((lane >> 3) & 1) * 16;

    float acc[2][NT][4];
    #pragma unroll
    for (int mt = 0; mt < 2; ++mt)
        #pragma unroll
        for (int nt = 0; nt < NT; ++nt)
            #pragma unroll
            for (int c = 0; c < 4; ++c) acc[mt][nt][c] = 0.f;

    for (int kc = 0; kc < T; ++kc) {
        int buf = kc & 1;
        if (LAST && kc == T - 1) asm volatile("cp.async.wait_group 0;");
        else                     asm volatile("cp.async.wait_group 1;");
        __syncthreads();                     // chunk kc visible to all

        const uint32_t bbase = sm_base + (uint32_t)(B_OFF + buf * BUFSZ)
                             + (uint32_t)((wn * (NT * 8) + b_noff) * 80 + b_kby);
        #pragma unroll
        for (int ks = 0; ks < 2; ++ks) {
            const int k0 = kc * 32 + ks * 16;
            uint32_t ahi[2][4], alo[2][4];
            #pragma unroll
            for (int mt = 0; mt < 2; ++mt) {
                uint32_t aaddr = sm_base +
                    (uint32_t)(((arow + mt * 16) * AS + k0 + acol) * 2);
                ldm_x4(ahi[mt], aaddr + A_HI_OFF);
                ldm_x4(alo[mt], aaddr + A_LO_OFF);
            }
            #pragma unroll
            for (int np = 0; np < NT / 2; ++np) {
                // one ldmatrix.x4 per split covers n16 x k16:
                // regs (0,1) = b-pair for nt=2np, (2,3) = for nt=2np+1
                uint32_t bh[4], bl[4];
                uint32_t ba = bbase + (uint32_t)(np * 16 * 80 + ks * 32);
                ldm_x4(bh, ba);
                ldm_x4(bl, ba + SSTR);
                // pass 1: hi*hi  (4 independent accs between same-acc reuse)
                #pragma unroll
                for (int q = 0; q < 2; ++q)
                    #pragma unroll
                    for (int mt = 0; mt < 2; ++mt)
                        mma_bf16(acc[mt][np * 2 + q], ahi[mt], bh[2 * q], bh[2 * q + 1]);
                // pass 2: lo*hi
                #pragma unroll
                for (int q = 0; q < 2; ++q)
                    #pragma unroll
                    for (int mt = 0; mt < 2; ++mt)
                        mma_bf16(acc[mt][np * 2 + q], alo[mt], bh[2 * q], bh[2 * q + 1]);
                // pass 3: hi*lo
                #pragma unroll
                for (int q = 0; q < 2; ++q)
                    #pragma unroll
                    for (int mt = 0; mt < 2; ++mt)
                        mma_bf16(acc[mt][np * 2 + q], ahi[mt], bl[2 * q], bl[2 * q + 1]);
            }
        }
        __syncthreads();                     // all reads of buf done

        // stream the next chunk into the freed buffer
        if (kc + 2 < T) {
            load_chunk<OUT>(sm_base + B_OFF + buf * BUFSZ,
                            gW + (size_t)(kc + 2) * 2 * OUT * 32);
        } else if (!LAST) {
            int nxt = kc + 2 - T;            // 0 or 1
            load_chunk<OUT_NEXT>(sm_base + B_OFF + buf * BUFSZ,
                                 gW_next + (size_t)nxt * 2 * OUT_NEXT * 32);
        }
    }

    // ---- epilogue: bias preloaded once, then ReLU/split or global store ----
    float2 bv[NT];
    #pragma unroll
    for (int nt = 0; nt < NT; ++nt)
        bv[nt] = __ldg((const float2*)(bias + wn * (NT * 8) + nt * 8 + (lane & 3) * 2));

    #pragma unroll
    for (int mt = 0; mt < 2; ++mt) {
        int row0 = wm * 32 + mt * 16 + (lane >> 2);
        #pragma unroll
        for (int nt = 0; nt < NT; ++nt) {
            int col = wn * (NT * 8) + nt * 8 + (lane & 3) * 2;
            float v0 = acc[mt][nt][0] + bv[nt].x, v1 = acc[mt][nt][1] + bv[nt].y;
            float v2 = acc[mt][nt][2] + bv[nt].x, v3 = acc[mt][nt][3] + bv[nt].y;
            if (LAST) {
                int n0 = nbase + row0, n1 = n0 + 8;
                if (n0 < n) {
                    float2 t = {v0, v1};
                    *(float2*)(out_g + (size_t)n0 * OUT + col) = t;
                }
                if (n1 < n) {
                    float2 t = {v2, v3};
                    *(float2*)(out_g + (size_t)n1 * OUT + col) = t;
                }
            } else {
                store_split(smem, row0,     col, fmaxf(v0, 0.f), fmaxf(v1, 0.f));
                store_split(smem, row0 + 8, col, fmaxf(v2, 0.f), fmaxf(v3, 0.f));
            }
        }
    }
    if (!LAST) __syncthreads();
}

// ---------------- kernel 3: HMMA MLP ----------------------------------------
__global__ void __launch_bounds__(TPB, 1)
mlp_mma_kernel(const float* __restrict__ x,
               const float* __restrict__ b1, const float* __restrict__ b2,
               const float* __restrict__ b3,
               float* __restrict__ out, int n)
{
    extern __shared__ char smem[];
    const uint32_t sm_base = smem_u32(smem);
    const int tid = threadIdx.x;
    const int nbase = blockIdx.x * 128;

    // prologue: chunks 0 and 1 of layer 1 (overlaps with A build below)
    load_chunk<256>(sm_base + B_OFF,         g_Wt);
    load_chunk<256>(sm_base + B_OFF + BUFSZ, g_Wt + 2 * 256 * 32);

    // Build A = concat(x, scatter-mean) as bf16 hi/lo, padded rows.
    {
        int m = tid >> 3, sub = tid & 7;     // 8 threads per node row
        int node = nbase + m;
        bool valid = node < n;
        float inv = 1.f;
        if (valid && sub >= 4) inv = 1.f / fmaxf(g_counts[node], 1.f);
        const float4* src = (sub < 4)
            ? (const float4*)x      + (size_t)node * 32 + sub * 8
            : (const float4*)g_sums + (size_t)node * 32 + (sub - 4) * 8;
        #pragma unroll
        for (int f = 0; f < 8; ++f) {
            float4 v = make_float4(0.f, 0.f, 0.f, 0.f);
            if (valid) {
                v = __ldg(src + f);
                if (sub >= 4) { v.x *= inv; v.y *= inv; v.z *= inv; v.w *= inv; }
            }
            int col = sub * 32 + f * 4;
            store_split(smem, m, col,     v.x, v.y);
            store_split(smem, m, col + 2, v.z, v.w);
        }
    }
    __syncthreads();

    run_layer<256, 256, 256, false>(smem, sm_base, g_Wt,          g_Wt + 131072,
                                    b1, nullptr, nbase, n);
    run_layer<256, 256, 128, false>(smem, sm_base, g_Wt + 131072, g_Wt + 262144,
                                    b2, nullptr, nbase, n);
    run_layer<256, 128, 128, true >(smem, sm_base, g_Wt + 262144, nullptr,
                                    b3, out, nbase, n);
}

// ---------------- launcher --------------------------------------------------
extern "C" void kernel_launch(void* const* d_in, const int* in_sizes, int n_in,
                              void* d_out, int out_size)
{
    const float* x          = (const float*)d_in[0];
    const int*   edge_index = (const int*)  d_in[1];
    const float* edge_attr  = (const float*)d_in[2];
    const float* W1 = (const float*)d_in[3];
    const float* b1 = (const float*)d_in[4];
    const float* W2 = (const float*)d_in[5];
    const float* b2 = (const float*)d_in[6];
    const float* W3 = (const float*)d_in[7];
    const float* b3 = (const float*)d_in[8];
    float* out = (float*)d_out;

    int n_nodes = in_sizes[0] / 128;
    int n_edges = in_sizes[1] / 2;
    const int* col = edge_index + n_edges;

    cudaFuncSetAttribute(mlp_mma_kernel,
                         cudaFuncAttributeMaxDynamicSharedMemorySize, SMEM_TOTAL);

    // 1) zero accumulators
    {
        int n4 = n_nodes * 32;
        zero_kernel<<<(n4 + 255) / 256, 256>>>(n_nodes);
    }
    // 2) prep weights (bf16 hi/lo, transposed + k-chunked)
    prep_kernel<<<1280, 256>>>(W1, W2, W3);
    // 3) scatter-add
    {
        long long total = (long long)n_edges * 32;
        scatter_kernel<<<(int)((total + 255) / 256), 256>>>(edge_attr, col, n_edges);
    }
    // 4) HMMA MLP
    {
        int blocks = (n_nodes + 127) / 128;
        mlp_mma_kernel<<<blocks, TPB, SMEM_TOTAL>>>(x, b1, b2, b3, out, n_nodes);
    }
}

// round 9
// speedup vs baseline: 1.1176x; 1.1176x over previous
#include <cuda_runtime.h>
#include <cuda_bf16.h>
#include <cstdint>

// ---------------- scratch (device globals: no allocation allowed) ----------
#define MAX_NODES 100000
__device__ __align__(16) float g_sums[(size_t)MAX_NODES * 128];
__device__ float g_counts[MAX_NODES];
// Transposed, k-chunked bf16 hi/lo weights:
// per layer: [kc][split][n][32] ; L1 @0 (131072), L2 @131072, L3 @262144
__device__ __align__(16) __nv_bfloat16 g_Wt[327680];

// ---------------- helpers ---------------------------------------------------
__device__ __forceinline__ uint32_t smem_u32(const void* p) {
    uint32_t a;
    asm("{ .reg .u64 t; cvta.to.shared.u64 t, %1; cvt.u32.u64 %0, t; }"
        : "=r"(a) : "l"(p));
    return a;
}
__device__ __forceinline__ void cp_async16(uint32_t saddr, const void* g) {
    asm volatile("cp.async.cg.shared.global [%0], [%1], 16;" :: "r"(saddr), "l"(g));
}
__device__ __forceinline__ void ldm_x4(uint32_t* r, uint32_t addr) {
    asm volatile("ldmatrix.sync.aligned.m8n8.x4.shared.b16 {%0,%1,%2,%3}, [%4];"
        : "=r"(r[0]), "=r"(r[1]), "=r"(r[2]), "=r"(r[3]) : "r"(addr));
}
__device__ __forceinline__ void mma_bf16(float* c, const uint32_t* a,
                                         uint32_t b0, uint32_t b1) {
    asm volatile("mma.sync.aligned.m16n8k16.row.col.f32.bf16.bf16.f32 "
        "{%0,%1,%2,%3}, {%4,%5,%6,%7}, {%8,%9}, {%0,%1,%2,%3};"
        : "+f"(c[0]), "+f"(c[1]), "+f"(c[2]), "+f"(c[3])
        : "r"(a[0]), "r"(a[1]), "r"(a[2]), "r"(a[3]), "r"(b0), "r"(b1));
}
__device__ __forceinline__ uint32_t pack_bf(__nv_bfloat16 a, __nv_bfloat16 b) {
    return (uint32_t)__bfloat16_as_ushort(a) | ((uint32_t)__bfloat16_as_ushort(b) << 16);
}

// smem layout (bytes)
constexpr int TPB      = 512;                 // 16 warps (4/SMSP) — R7 config
constexpr int AS       = 264;                 // A row stride (elements)
constexpr int A_HI_OFF = 0;                   // 128*264*2 = 67584
constexpr int A_LO_OFF = 67584;
constexpr int B_OFF    = 135168;
constexpr int BUFSZ    = 40960;               // one B buffer (OUT=256 worst case)
constexpr int SMEM_TOTAL = B_OFF + 2 * BUFSZ; // 217088

__device__ __forceinline__ void store_split(char* smem, int row, int col,
                                            float v0, float v1) {
    __nv_bfloat16 h0 = __float2bfloat16(v0), h1 = __float2bfloat16(v1);
    __nv_bfloat16 l0 = __float2bfloat16(v0 - __bfloat162float(h0));
    __nv_bfloat16 l1 = __float2bfloat16(v1 - __bfloat162float(h1));
    uint32_t off = (uint32_t)(row * AS + col) * 2;
    *(uint32_t*)(smem + A_HI_OFF + off) = pack_bf(h0, h1);
    *(uint32_t*)(smem + A_LO_OFF + off) = pack_bf(l0, l1);
}

// ---------------- kernel 1: zero the scatter accumulators ------------------
__global__ void zero_kernel(int n_nodes) {
    int i = blockIdx.x * blockDim.x + threadIdx.x;
    int n4 = n_nodes * 32;
    if (i < n4) ((float4*)g_sums)[i] = make_float4(0.f, 0.f, 0.f, 0.f);
    if (i < n_nodes) g_counts[i] = 0.f;
}

// ---------------- kernel 2: scatter-add (vector atomics) -------------------
__global__ void scatter_kernel(const float* __restrict__ edge_attr,
                               const int*   __restrict__ col,
                               int n_edges) {
    int t = blockIdx.x * blockDim.x + threadIdx.x;
    int e = t >> 5;
    int lane = t & 31;
    if (e >= n_edges) return;
    int c = __ldg(col + e);
    float4 v = ((const float4*)edge_attr)[(size_t)e * 32 + lane];
    float* dst = g_sums + (size_t)c * 128 + lane * 4;
    asm volatile("red.global.add.v4.f32 [%0], {%1,%2,%3,%4};"
                 :: "l"(dst), "f"(v.x), "f"(v.y), "f"(v.z), "f"(v.w) : "memory");
    if (lane == 0) atomicAdd(g_counts + c, 1.0f);
}

// ---------------- kernel: prep weights -> g_Wt (coalesced via smem tile) ---
// Layout per layer: [kc][split(hi=0,lo=1)][n][32 k], n-major rows (W^T).
// 80 blocks: layer1 tiles 0..31 (kc x nb), layer2 32..63, layer3 64..79.
__global__ void prep_kernel(const float* __restrict__ W1,
                            const float* __restrict__ W2,
                            const float* __restrict__ W3) {
    __shared__ float tile[32][65];
    int b = blockIdx.x;
    const float* W; int base, OUT, t;
    if (b < 32)      { W = W1; base = 0;      OUT = 256; t = b; }
    else if (b < 64) { W = W2; base = 131072; OUT = 256; t = b - 32; }
    else             { W = W3; base = 262144; OUT = 128; t = b - 64; }
    int nbt = OUT / 64;
    int kc = t / nbt, nb = t % nbt;
    int tid = threadIdx.x;
    #pragma unroll
    for (int i = 0; i < 8; ++i) {             // coalesced read of 32k x 64n tile
        int idx = tid + i * 256;
        int kr = idx >> 6, nc = idx & 63;
        tile[kr][nc] = __ldg(W + (size_t)(kc * 32 + kr) * OUT + nb * 64 + nc);
    }
    __syncthreads();
    int nn = tid >> 2, kq = tid & 3;          // each thread: 8 consecutive kk
    uint4 vh, vl;
    uint32_t* ph = (uint32_t*)&vh;
    uint32_t* pl = (uint32_t*)&vl;
    #pragma unroll
    for (int j = 0; j < 4; ++j) {
        float w0 = tile[kq * 8 + 2 * j][nn];
        float w1 = tile[kq * 8 + 2 * j + 1][nn];
        __nv_bfloat16 h0 = __float2bfloat16(w0), h1 = __float2bfloat16(w1);
        __nv_bfloat16 l0 = __float2bfloat16(w0 - __bfloat162float(h0));
        __nv_bfloat16 l1 = __float2bfloat16(w1 - __bfloat162float(h1));
        ph[j] = pack_bf(h0, h1);
        pl[j] = pack_bf(l0, l1);
    }
    size_t o_hi = (size_t)base + ((size_t)(kc * 2 + 0) * OUT + nb * 64 + nn) * 32 + kq * 8;
    size_t o_lo = (size_t)base + ((size_t)(kc * 2 + 1) * OUT + nb * 64 + nn) * 32 + kq * 8;
    *(uint4*)(g_Wt + o_hi) = vh;              // 16B coalesced-ish writes
    *(uint4*)(g_Wt + o_lo) = vl;
}

// ---------------- B chunk loader (linear cp.async into padded rows) --------
template<int OUT>
__device__ __forceinline__ void load_chunk(uint32_t bdst, const __nv_bfloat16* gsrc) {
    constexpr int UNITS = OUT * 8;         // 16B units in a chunk (both splits)
    constexpr int SSTR  = OUT * 80;        // bytes per split in smem
    #pragma unroll
    for (int u = threadIdx.x; u < UNITS; u += TPB) {
        int s = u / (UNITS / 2);
        int v = u % (UNITS / 2);
        int nn = v >> 2, part = v & 3;
        uint32_t dst = bdst + s * SSTR + nn * 80 + part * 16;
        cp_async16(dst, (const char*)gsrc + (size_t)u * 16);
    }
    asm volatile("cp.async.commit_group;");
}

// ---------------- one MLP layer on HMMA -------------------------------------
// Warp grid 4(m) x 4(n). Invariant at entry: this layer's chunks 0 and 1
// already committed, chunk c in buffer c&1; during the loop chunk kc+2 (or
// the next layer's chunks 0/1) is issued after the compute sync of chunk kc.
// T = IN/32 k-chunks (IN = 256 for all layers). B fragments double-buffered:
// the ldmatrix for np+1 issues before the 12 MMAs of np.
template<int IN, int OUT, int OUT_NEXT, bool LAST>
__device__ __forceinline__ void run_layer(char* smem, uint32_t sm_base,
                                          const __nv_bfloat16* gW,
                                          const __nv_bfloat16* gW_next,
                                          const float* __restrict__ bias,
                                          float* __restrict__ out_g,
                                          int nbase, int n)
{
    const int lane = threadIdx.x & 31, wid = threadIdx.x >> 5;
    const int wm = wid >> 2, wn = wid & 3;
    constexpr int NT   = OUT / 32;          // n8-tiles per warp
    constexpr int T    = IN / 32;           // k-chunks this layer (=8)
    constexpr int SSTR = OUT * 80;          // bytes per split in a B buffer

    const int arow = wm * 32 + (lane & 15);
    const int acol = (lane >> 4) * 8;
    // B ldmatrix lane mapping: lane l -> row (l&7) of matrix l>>3.
    const int b_noff = ((lane >> 4) & 1) * 8 + (lane & 7);
    const int b_kby  = ((lane >> 3) & 1) * 16;

    float acc[2][NT][4];
    #pragma unroll
    for (int mt = 0; mt < 2; ++mt)
        #pragma unroll
        for (int nt = 0; nt < NT; ++nt)
            #pragma unroll
            for (int c = 0; c < 4; ++c) acc[mt][nt][c] = 0.f;

    for (int kc = 0; kc < T; ++kc) {
        int buf = kc & 1;
        if (LAST && kc == T - 1) asm volatile("cp.async.wait_group 0;");
        else                     asm volatile("cp.async.wait_group 1;");
        __syncthreads();                     // chunk kc visible to all

        const uint32_t bbase = sm_base + (uint32_t)(B_OFF + buf * BUFSZ)
                             + (uint32_t)((wn * (NT * 8) + b_noff) * 80 + b_kby);
        #pragma unroll
        for (int ks = 0; ks < 2; ++ks) {
            const int k0 = kc * 32 + ks * 16;
            uint32_t ahi[2][4], alo[2][4];
            #pragma unroll
            for (int mt = 0; mt < 2; ++mt) {
                uint32_t aaddr = sm_base +
                    (uint32_t)(((arow + mt * 16) * AS + k0 + acol) * 2);
                ldm_x4(ahi[mt], aaddr + A_HI_OFF);
                ldm_x4(alo[mt], aaddr + A_LO_OFF);
            }
            // B fragment double-buffer: prefetch np+1 before computing np
            uint32_t bh[2][4], bl[2][4];
            {
                uint32_t ba = bbase + (uint32_t)(ks * 32);
                ldm_x4(bh[0], ba);
                ldm_x4(bl[0], ba + SSTR);
            }
            #pragma unroll
            for (int np = 0; np < NT / 2; ++np) {
                const int cur = np & 1, nxt = cur ^ 1;
                if (np + 1 < NT / 2) {
                    uint32_t ba = bbase + (uint32_t)((np + 1) * 16 * 80 + ks * 32);
                    ldm_x4(bh[nxt], ba);
                    ldm_x4(bl[nxt], ba + SSTR);
                }
                // pass 1: hi*hi  (4 independent accs between same-acc reuse)
                #pragma unroll
                for (int q = 0; q < 2; ++q)
                    #pragma unroll
                    for (int mt = 0; mt < 2; ++mt)
                        mma_bf16(acc[mt][np * 2 + q], ahi[mt],
                                 bh[cur][2 * q], bh[cur][2 * q + 1]);
                // pass 2: lo*hi
                #pragma unroll
                for (int q = 0; q < 2; ++q)
                    #pragma unroll
                    for (int mt = 0; mt < 2; ++mt)
                        mma_bf16(acc[mt][np * 2 + q], alo[mt],
                                 bh[cur][2 * q], bh[cur][2 * q + 1]);
                // pass 3: hi*lo
                #pragma unroll
                for (int q = 0; q < 2; ++q)
                    #pragma unroll
                    for (int mt = 0; mt < 2; ++mt)
                        mma_bf16(acc[mt][np * 2 + q], ahi[mt],
                                 bl[cur][2 * q], bl[cur][2 * q + 1]);
            }
        }
        __syncthreads();                     // all reads of buf done

        // stream the next chunk into the freed buffer
        if (kc + 2 < T) {
            load_chunk<OUT>(sm_base + B_OFF + buf * BUFSZ,
                            gW + (size_t)(kc + 2) * 2 * OUT * 32);
        } else if (!LAST) {
            int nxt = kc + 2 - T;            // 0 or 1
            load_chunk<OUT_NEXT>(sm_base + B_OFF + buf * BUFSZ,
                                 gW_next + (size_t)nxt * 2 * OUT_NEXT * 32);
        }
    }

    // ---- epilogue: bias preloaded once, then ReLU/split or global store ----
    float2 bv[NT];
    #pragma unroll
    for (int nt = 0; nt < NT; ++nt)
        bv[nt] = __ldg((const float2*)(bias + wn * (NT * 8) + nt * 8 + (lane & 3) * 2));

    #pragma unroll
    for (int mt = 0; mt < 2; ++mt) {
        int row0 = wm * 32 + mt * 16 + (lane >> 2);
        #pragma unroll
        for (int nt = 0; nt < NT; ++nt) {
            int col = wn * (NT * 8) + nt * 8 + (lane & 3) * 2;
            float v0 = acc[mt][nt][0] + bv[nt].x, v1 = acc[mt][nt][1] + bv[nt].y;
            float v2 = acc[mt][nt][2] + bv[nt].x, v3 = acc[mt][nt][3] + bv[nt].y;
            if (LAST) {
                int n0 = nbase + row0, n1 = n0 + 8;
                if (n0 < n) {
                    float2 t = {v0, v1};
                    *(float2*)(out_g + (size_t)n0 * OUT + col) = t;
                }
                if (n1 < n) {
                    float2 t = {v2, v3};
                    *(float2*)(out_g + (size_t)n1 * OUT + col) = t;
                }
            } else {
                store_split(smem, row0,     col, fmaxf(v0, 0.f), fmaxf(v1, 0.f));
                store_split(smem, row0 + 8, col, fmaxf(v2, 0.f), fmaxf(v3, 0.f));
            }
        }
    }
    if (!LAST) __syncthreads();
}

// ---------------- kernel 3: HMMA MLP ----------------------------------------
__global__ void __launch_bounds__(TPB, 1)
mlp_mma_kernel(const float* __restrict__ x,
               const float* __restrict__ b1, const float* __restrict__ b2,
               const float* __restrict__ b3,
               float* __restrict__ out, int n)
{
    extern __shared__ char smem[];
    const uint32_t sm_base = smem_u32(smem);
    const int tid = threadIdx.x;
    const int nbase = blockIdx.x * 128;

    // prologue: chunks 0 and 1 of layer 1 (overlaps with A build below)
    load_chunk<256>(sm_base + B_OFF,         g_Wt);
    load_chunk<256>(sm_base + B_OFF + BUFSZ, g_Wt + 2 * 256 * 32);

    // Build A = concat(x, scatter-mean) as bf16 hi/lo, padded rows.
    {
        int m = tid >> 2, q = tid & 3;
        int node = nbase + m;
        bool valid = node < n;
        const float4* src = (q < 2)
            ? (const float4*)x      + (size_t)node * 32 + q * 16
            : (const float4*)g_sums + (size_t)node * 32 + (q - 2) * 16;
        float inv = 1.f;
        if (valid && q >= 2) inv = 1.f / fmaxf(g_counts[node], 1.f);
        #pragma unroll 4
        for (int f = 0; f < 16; ++f) {
            float4 v = make_float4(0.f, 0.f, 0.f, 0.f);
            if (valid) {
                v = __ldg(src + f);
                if (q >= 2) { v.x *= inv; v.y *= inv; v.z *= inv; v.w *= inv; }
            }
            int col = q * 64 + f * 4;
            store_split(smem, m, col,     v.x, v.y);
            store_split(smem, m, col + 2, v.z, v.w);
        }
    }
    __syncthreads();

    run_layer<256, 256, 256, false>(smem, sm_base, g_Wt,          g_Wt + 131072,
                                    b1, nullptr, nbase, n);
    run_layer<256, 256, 128, false>(smem, sm_base, g_Wt + 131072, g_Wt + 262144,
                                    b2, nullptr, nbase, n);
    run_layer<256, 128, 128, true >(smem, sm_base, g_Wt + 262144, nullptr,
                                    b3, out, nbase, n);
}

// ---------------- launcher --------------------------------------------------
extern "C" void kernel_launch(void* const* d_in, const int* in_sizes, int n_in,
                              void* d_out, int out_size)
{
    const float* x          = (const float*)d_in[0];
    const int*   edge_index = (const int*)  d_in[1];
    const float* edge_attr  = (const float*)d_in[2];
    const float* W1 = (const float*)d_in[3];
    const float* b1 = (const float*)d_in[4];
    const float* W2 = (const float*)d_in[5];
    const float* b2 = (const float*)d_in[6];
    const float* W3 = (const float*)d_in[7];
    const float* b3 = (const float*)d_in[8];
    float* out = (float*)d_out;

    int n_nodes = in_sizes[0] / 128;
    int n_edges = in_sizes[1] / 2;
    const int* col = edge_index + n_edges;

    cudaFuncSetAttribute(mlp_mma_kernel,
                         cudaFuncAttributeMaxDynamicSharedMemorySize, SMEM_TOTAL);

    // 1) zero accumulators
    {
        int n4 = n_nodes * 32;
        zero_kernel<<<(n4 + 255) / 256, 256>>>(n_nodes);
    }
    // 2) prep weights (bf16 hi/lo, transposed + k-chunked, coalesced)
    prep_kernel<<<80, 256>>>(W1, W2, W3);
    // 3) scatter-add
    {
        long long total = (long long)n_edges * 32;
        scatter_kernel<<<(int)((total + 255) / 256), 256>>>(edge_attr, col, n_edges);
    }
    // 4) HMMA MLP
    {
        int blocks = (n_nodes + 127) / 128;
        mlp_mma_kernel<<<blocks, TPB, SMEM_TOTAL>>>(x, b1, b2, b3, out, n_nodes);
    }
}